// round 10
// baseline (speedup 1.0000x reference)
#include <cuda_runtime.h>
#include <cuda_fp16.h>
#include <cstdint>

// ---------------------------------------------------------------------------
// Problem constants
// ---------------------------------------------------------------------------
#define N_NODES  50000
#define N_EDGES  800000
#define NODE_IN  128
#define EDGE_OUT 64
#define DIN      320
#define HID      512
#define NODE_OUT 128
#define CAP      96
#define MPAD     50048          // 391 * 128

// ---------------------------------------------------------------------------
// Static device scratch (__device__ globals only; no allocations)
// ---------------------------------------------------------------------------
__device__ int d_flag;
__device__ int d_cursor[N_NODES];
__device__ int d_bucket[N_NODES * CAP];
__device__ __align__(16) unsigned short d_A1[(size_t)MPAD * DIN];     // H  (fp16)
__device__ __align__(16) unsigned short d_W1p[HID * DIN];             // W1^T fp16
__device__ __align__(16) unsigned short d_W2p[NODE_OUT * HID];        // W2^T fp16

// ---------------------------------------------------------------------------
// Helpers
// ---------------------------------------------------------------------------
__device__ __forceinline__ uint32_t smem_u32_(const void* p) {
    uint32_t a;
    asm("{ .reg .u64 t; cvta.to.shared.u64 t, %1; cvt.u32.u64 %0, t; }" : "=r"(a) : "l"(p));
    return a;
}

__device__ __forceinline__ void cpa16(uint32_t s, const void* g) {
    asm volatile("cp.async.cg.shared.global [%0], [%1], 16;"
                 :: "r"(s), "l"(__cvta_generic_to_global(g)));
}
#define CP_COMMIT() asm volatile("cp.async.commit_group;")
#define CP_WAIT2()  asm volatile("cp.async.wait_group 2;")
#define CP_WAIT0()  asm volatile("cp.async.wait_group 0;")

#define LDSM4(r, a)                                                          \
    asm volatile("ldmatrix.sync.aligned.m8n8.x4.shared.b16 {%0,%1,%2,%3}, [%4];" \
        : "=r"((r)[0]), "=r"((r)[1]), "=r"((r)[2]), "=r"((r)[3]) : "r"(a))

__device__ __forceinline__ void mma16816(float* c, const uint32_t* a, const uint32_t* b) {
    asm volatile(
        "mma.sync.aligned.m16n8k16.row.col.f32.f16.f16.f32 "
        "{%0,%1,%2,%3}, {%4,%5,%6,%7}, {%8,%9}, {%0,%1,%2,%3};"
        : "+f"(c[0]), "+f"(c[1]), "+f"(c[2]), "+f"(c[3])
        : "r"(a[0]), "r"(a[1]), "r"(a[2]), "r"(a[3]), "r"(b[0]), "r"(b[1]));
}

// ---------------------------------------------------------------------------
// K0: init cursors + flag
// ---------------------------------------------------------------------------
__global__ void k_init() {
    int i = blockIdx.x * blockDim.x + threadIdx.x;
    if (i < N_NODES) d_cursor[i] = 0;
    if (i == 0) d_flag = 0;
}

// K1: dtype probe (int64 vs int32 edge_index)
__global__ void k_probe(const void* __restrict__ ei) {
    const long long v = ((const long long*)ei)[threadIdx.x];
    if (v < 0 || v >= (long long)N_NODES) d_flag = 1;
}

// K2: bucket edges by destination node
__global__ void k_bucket(const void* __restrict__ ei) {
    int e = blockIdx.x * blockDim.x + threadIdx.x;
    if (e >= N_EDGES) return;
    int c = d_flag ? ((const int*)ei)[N_EDGES + e]
                   : (int)((const long long*)ei)[N_EDGES + e];
    int pos = atomicAdd(&d_cursor[c], 1);
    if (pos < CAP) d_bucket[c * CAP + pos] = e;
}

// K2b: transpose weights + round to fp16
__global__ void k_prepW(const float* __restrict__ W1, const float* __restrict__ W2) {
    int i = blockIdx.x * blockDim.x + threadIdx.x;
    const int N1 = HID * DIN;
    if (i < N1) {
        int n = i / DIN, k = i % DIN;
        d_W1p[i] = __half_as_ushort(__float2half_rn(W1[(size_t)k * HID + n]));
    } else if (i < N1 + NODE_OUT * HID) {
        int j = i - N1;
        int n = j / HID, k = j % HID;
        d_W2p[j] = __half_as_ushort(__float2half_rn(W2[(size_t)k * NODE_OUT + n]));
    }
}

// ---------------------------------------------------------------------------
// K3: per-node reduce -> fp16 H row [x | sum | max | mean]
// ---------------------------------------------------------------------------
__global__ void __launch_bounds__(64) k_buildH(const float* __restrict__ x,
                                               const float* __restrict__ edge_attr) {
    __shared__ int se[CAP];
    __shared__ __align__(16) unsigned short rowbuf[DIN];
    const int n = blockIdx.x;
    const int f = threadIdx.x;

    if (n >= N_NODES) {            // zero padding rows for determinism
        uint4* g = (uint4*)(d_A1 + (size_t)n * DIN);
        uint4 z = make_uint4(0, 0, 0, 0);
        for (int w = f; w < DIN / 8; w += 64) g[w] = z;
        return;
    }

    const int total = d_cursor[n];
    const int ec = total < CAP ? total : CAP;
    for (int i = f; i < ec; i += 64) se[i] = d_bucket[n * CAP + i];
    __syncthreads();

    const float NEG_INF = __int_as_float(0xff800000u);
    float s0 = 0.f, s1 = 0.f, s2 = 0.f, s3 = 0.f;
    float m0 = NEG_INF, m1 = NEG_INF, m2 = NEG_INF, m3 = NEG_INF;

    int i = 0;
    for (; i + 4 <= ec; i += 4) {
        float v0 = __ldg(&edge_attr[(size_t)se[i + 0] * EDGE_OUT + f]);
        float v1 = __ldg(&edge_attr[(size_t)se[i + 1] * EDGE_OUT + f]);
        float v2 = __ldg(&edge_attr[(size_t)se[i + 2] * EDGE_OUT + f]);
        float v3 = __ldg(&edge_attr[(size_t)se[i + 3] * EDGE_OUT + f]);
        s0 += v0; s1 += v1; s2 += v2; s3 += v3;
        m0 = fmaxf(m0, v0); m1 = fmaxf(m1, v1);
        m2 = fmaxf(m2, v2); m3 = fmaxf(m3, v3);
    }
    for (; i < ec; i++) {
        float v = __ldg(&edge_attr[(size_t)se[i] * EDGE_OUT + f]);
        s0 += v; m0 = fmaxf(m0, v);
    }
    const float sum = (s0 + s1) + (s2 + s3);
    float mx = fmaxf(fmaxf(m0, m1), fmaxf(m2, m3));
    if (ec == 0) mx = 0.f;
    const float mean = sum / fmaxf((float)total, 1.f);

    float vals[5];
    vals[0] = x[(size_t)n * NODE_IN + f];
    vals[1] = x[(size_t)n * NODE_IN + 64 + f];
    vals[2] = sum; vals[3] = mx; vals[4] = mean;
#pragma unroll
    for (int c5 = 0; c5 < 5; c5++)
        rowbuf[c5 * 64 + f] = __half_as_ushort(__float2half_rn(vals[c5]));
    __syncthreads();

    uint4* g = (uint4*)(d_A1 + (size_t)n * DIN);
    const uint4* s4 = (const uint4*)rowbuf;
    for (int w = f; w < DIN / 8; w += 64) g[w] = s4[w];
}

// ---------------------------------------------------------------------------
// K4: FUSED MLP. One CTA owns 128 rows.
// Phase 1: flat 40-iter pipelined loop (4 N-chunks x K=320) -> relu fp16 into
//          SMEM Hm tile (128 x 512 halfs, XOR-swizzled, 128KB, no padding).
// Phase 2: K=512 GEMM; A ldmatrix'd directly from SMEM Hm, B (W2) pipelined.
// SMEM: [0, 81920) 4-slot pipeline ring; [81920, 212992) Hm tile.
// ---------------------------------------------------------------------------
#define SROW     80
#define SLOTB    20480
#define HM_OFF   81920
#define SMEM_FUSED (HM_OFF + 128 * 1024)   // 212992

__global__ void __launch_bounds__(256, 1)
k_fused(const unsigned short* __restrict__ gA,
        const unsigned short* __restrict__ gB1,
        const unsigned short* __restrict__ gB2,
        const float* __restrict__ b1v, const float* __restrict__ b2v,
        float* __restrict__ outp) {
    extern __shared__ __align__(16) char sm[];
    const uint32_t sb = smem_u32_(sm);
    const uint32_t hmb = sb + HM_OFF;
    char* hmp = sm + HM_OFF;

    const int tid = threadIdx.x, L = tid & 31, wid = tid >> 5;
    const int wm = wid >> 2, wn = wid & 3;
    const int row0 = blockIdx.x * 128;

    const int r0c = tid >> 2, q0c = (tid & 3) * 16;   // rows 0..63
    const int r1c = r0c + 64;                          // rows 64..127

#define LS1(s, nc, k0)                                                           \
    do {                                                                         \
        uint32_t Ab_ = sb + (s) * SLOTB, Bb_ = Ab_ + 10240;                      \
        cpa16(Ab_ + r0c * SROW + q0c, gA + (size_t)(row0 + r0c) * DIN + (k0) + (q0c >> 1)); \
        cpa16(Ab_ + r1c * SROW + q0c, gA + (size_t)(row0 + r1c) * DIN + (k0) + (q0c >> 1)); \
        cpa16(Bb_ + r0c * SROW + q0c, gB1 + (size_t)((nc) * 128 + r0c) * DIN + (k0) + (q0c >> 1)); \
        cpa16(Bb_ + r1c * SROW + q0c, gB1 + (size_t)((nc) * 128 + r1c) * DIN + (k0) + (q0c >> 1)); \
    } while (0)

#define LS2(s, k0)                                                               \
    do {                                                                         \
        uint32_t Bb_ = sb + (s) * SLOTB;                                         \
        cpa16(Bb_ + r0c * SROW + q0c, gB2 + (size_t)r0c * HID + (k0) + (q0c >> 1)); \
        cpa16(Bb_ + r1c * SROW + q0c, gB2 + (size_t)r1c * HID + (k0) + (q0c >> 1)); \
    } while (0)

    float acc[4][4][4];
#pragma unroll
    for (int a = 0; a < 4; a++)
#pragma unroll
        for (int b = 0; b < 4; b++)
#pragma unroll
            for (int c = 0; c < 4; c++) acc[a][b][c] = 0.f;

    // ---------------- Phase 1: 4 chunks x NT=10, flat pipelined ----------------
#pragma unroll
    for (int l = 0; l < 3; l++) { LS1(l, 0, l << 5); CP_COMMIT(); }   // l/10==0

    int nc = 0;
    for (int g = 0; g < 40; g++) {
        CP_WAIT2();
        __syncthreads();
        const int l = g + 3;
        if (l < 40) LS1(l & 3, l / 10, (l % 10) << 5);
        CP_COMMIT();

        const uint32_t Ab = sb + (g & 3) * SLOTB;
        const uint32_t Bb = Ab + 10240;
        const uint32_t aBase = Ab + (uint32_t)((wm * 64 + (L & 15)) * SROW + ((L >> 4) << 4));
        const uint32_t bBase = Bb + (uint32_t)((wn * 32 + (L & 7) + ((L >> 4) << 3)) * SROW
                                               + (((L >> 3) & 1) << 4));
#pragma unroll
        for (int ks = 0; ks < 2; ks++) {
            uint32_t afr[4][4], bfr[2][4];
#pragma unroll
            for (int mf = 0; mf < 4; mf++) LDSM4(afr[mf], aBase + mf * 16 * SROW + ks * 32);
#pragma unroll
            for (int nb = 0; nb < 2; nb++) LDSM4(bfr[nb], bBase + nb * 16 * SROW + ks * 32);
#pragma unroll
            for (int mf = 0; mf < 4; mf++)
#pragma unroll
                for (int nf = 0; nf < 4; nf++)
                    mma16816(acc[mf][nf], afr[mf], &bfr[nf >> 1][(nf & 1) * 2]);
        }

        if ((g % 10) == 9) {
            // chunk epilogue: bias+relu+fp16 -> swizzled Hm (warp-local STS)
#pragma unroll
            for (int mf = 0; mf < 4; mf++) {
                const int r = wm * 64 + mf * 16 + (L >> 2);
#pragma unroll
                for (int nf = 0; nf < 4; nf++) {
                    const int cl = wn * 32 + nf * 8 + (L & 3) * 2;
                    const int gc = nc * 128 + cl;
                    const float bb0 = __ldg(b1v + gc), bb1 = __ldg(b1v + gc + 1);
                    const int unit = gc >> 3, bib = (gc & 7) << 1;
                    __half2 h0 = __floats2half2_rn(fmaxf(acc[mf][nf][0] + bb0, 0.f),
                                                   fmaxf(acc[mf][nf][1] + bb1, 0.f));
                    *(__half2*)(hmp + r * 1024 + ((unit ^ (r & 7)) << 4) + bib) = h0;
                    const int r2 = r + 8;
                    __half2 h1 = __floats2half2_rn(fmaxf(acc[mf][nf][2] + bb0, 0.f),
                                                   fmaxf(acc[mf][nf][3] + bb1, 0.f));
                    *(__half2*)(hmp + r2 * 1024 + ((unit ^ (r2 & 7)) << 4) + bib) = h1;
                    acc[mf][nf][0] = acc[mf][nf][1] = acc[mf][nf][2] = acc[mf][nf][3] = 0.f;
                }
            }
            nc++;
        }
    }
    CP_WAIT0();
    __syncthreads();          // Hm complete & visible; pipeline slots free

    // ---------------- Phase 2: K=512, A from SMEM Hm, B=W2 pipelined ----------
#pragma unroll
    for (int p = 0; p < 3; p++) { LS2(p, p << 5); CP_COMMIT(); }

    for (int kt = 0; kt < 16; kt++) {
        CP_WAIT2();
        __syncthreads();
        if (kt + 3 < 16) LS2((kt + 3) & 3, (kt + 3) << 5);
        CP_COMMIT();

        const uint32_t Bb = sb + (kt & 3) * SLOTB;
        const uint32_t bBase = Bb + (uint32_t)((wn * 32 + (L & 7) + ((L >> 4) << 3)) * SROW
                                               + (((L >> 3) & 1) << 4));
#pragma unroll
        for (int ks = 0; ks < 2; ks++) {
            uint32_t afr[4][4], bfr[2][4];
#pragma unroll
            for (int mf = 0; mf < 4; mf++) {
                const int ar = wm * 64 + mf * 16 + (L & 15);
                const int unit = kt * 4 + ks * 2 + (L >> 4);
                LDSM4(afr[mf], hmb + ar * 1024 + ((unit ^ (ar & 7)) << 4));
            }
#pragma unroll
            for (int nb = 0; nb < 2; nb++) LDSM4(bfr[nb], bBase + nb * 16 * SROW + ks * 32);
#pragma unroll
            for (int mf = 0; mf < 4; mf++)
#pragma unroll
                for (int nf = 0; nf < 4; nf++)
                    mma16816(acc[mf][nf], afr[mf], &bfr[nf >> 1][(nf & 1) * 2]);
        }
    }

    // final epilogue: fp32 + b2, row-guarded
#pragma unroll
    for (int mf = 0; mf < 4; mf++) {
        const int r = row0 + wm * 64 + mf * 16 + (L >> 2);
#pragma unroll
        for (int nf = 0; nf < 4; nf++) {
            const int c = wn * 32 + nf * 8 + (L & 3) * 2;
            const float bb0 = __ldg(b2v + c), bb1 = __ldg(b2v + c + 1);
            if (r < N_NODES) {
                outp[(size_t)r * NODE_OUT + c]     = acc[mf][nf][0] + bb0;
                outp[(size_t)r * NODE_OUT + c + 1] = acc[mf][nf][1] + bb1;
            }
            if (r + 8 < N_NODES) {
                outp[(size_t)(r + 8) * NODE_OUT + c]     = acc[mf][nf][2] + bb0;
                outp[(size_t)(r + 8) * NODE_OUT + c + 1] = acc[mf][nf][3] + bb1;
            }
        }
    }
#undef LS1
#undef LS2
}

// ---------------------------------------------------------------------------
// Host launcher (graph-capturable: kernel launches only)
// ---------------------------------------------------------------------------
extern "C" void kernel_launch(void* const* d_in, const int* in_sizes, int n_in,
                              void* d_out, int out_size) {
    const float* x         = (const float*)d_in[0];
    const void*  ei        = d_in[1];
    const float* edge_attr = (const float*)d_in[2];
    const float* W1 = (const float*)d_in[5];
    const float* b1 = (const float*)d_in[6];
    const float* W2 = (const float*)d_in[7];
    const float* b2 = (const float*)d_in[8];
    float* out = (float*)d_out;

    void *pA1, *pW1p, *pW2p;
    cudaGetSymbolAddress(&pA1, d_A1);
    cudaGetSymbolAddress(&pW1p, d_W1p);
    cudaGetSymbolAddress(&pW2p, d_W2p);

    cudaFuncSetAttribute(k_fused, cudaFuncAttributeMaxDynamicSharedMemorySize, SMEM_FUSED);

    k_init<<<(N_NODES + 255) / 256, 256>>>();
    k_probe<<<1, 256>>>(ei);
    k_bucket<<<(N_EDGES + 255) / 256, 256>>>(ei);
    {
        const int tot = HID * DIN + NODE_OUT * HID;
        k_prepW<<<(tot + 255) / 256, 256>>>(W1, W2);
    }
    k_buildH<<<MPAD, 64>>>(x, edge_attr);

    // Fused MLP: relu(H@W1+b1)@W2 + b2, one CTA per 128 rows
    k_fused<<<MPAD / 128, 256, SMEM_FUSED>>>(
        (const unsigned short*)pA1, (const unsigned short*)pW1p,
        (const unsigned short*)pW2p, b1, b2, out);
}

// round 11
// speedup vs baseline: 1.0171x; 1.0171x over previous
#include <cuda_runtime.h>
#include <cuda_fp16.h>
#include <cstdint>

// ---------------------------------------------------------------------------
// Problem constants
// ---------------------------------------------------------------------------
#define N_NODES  50000
#define N_EDGES  800000
#define NODE_IN  128
#define EDGE_OUT 64
#define DIN      320
#define HID      512
#define NODE_OUT 128
#define CAP      96
#define MPAD     50048          // 391 * 128 (also divisible by 64)

// ---------------------------------------------------------------------------
// Static device scratch (__device__ globals only; no allocations)
// ---------------------------------------------------------------------------
__device__ int d_flag;
__device__ int d_cursor[N_NODES];
__device__ int d_bucket[N_NODES * CAP];
__device__ __align__(16) unsigned short d_A1[(size_t)MPAD * DIN];     // H  (fp16)
__device__ __align__(16) unsigned short d_Hm[(size_t)MPAD * HID];     // relu(HW1+b1) fp16
__device__ __align__(16) unsigned short d_W1p[HID * DIN];             // W1^T fp16
__device__ __align__(16) unsigned short d_W2p[NODE_OUT * HID];        // W2^T fp16

// ---------------------------------------------------------------------------
// Helpers
// ---------------------------------------------------------------------------
__device__ __forceinline__ uint32_t smem_u32_(const void* p) {
    uint32_t a;
    asm("{ .reg .u64 t; cvta.to.shared.u64 t, %1; cvt.u32.u64 %0, t; }" : "=r"(a) : "l"(p));
    return a;
}

__device__ __forceinline__ void cpa16(uint32_t s, const void* g) {
    asm volatile("cp.async.cg.shared.global [%0], [%1], 16;"
                 :: "r"(s), "l"(__cvta_generic_to_global(g)));
}
#define CP_COMMIT() asm volatile("cp.async.commit_group;")
#define CP_WAIT0()  asm volatile("cp.async.wait_group 0;")

#define LDSM4(r, a)                                                          \
    asm volatile("ldmatrix.sync.aligned.m8n8.x4.shared.b16 {%0,%1,%2,%3}, [%4];" \
        : "=r"((r)[0]), "=r"((r)[1]), "=r"((r)[2]), "=r"((r)[3]) : "r"(a))

__device__ __forceinline__ void mma16816(float* c, const uint32_t* a, const uint32_t* b) {
    asm volatile(
        "mma.sync.aligned.m16n8k16.row.col.f32.f16.f16.f32 "
        "{%0,%1,%2,%3}, {%4,%5,%6,%7}, {%8,%9}, {%0,%1,%2,%3};"
        : "+f"(c[0]), "+f"(c[1]), "+f"(c[2]), "+f"(c[3])
        : "r"(a[0]), "r"(a[1]), "r"(a[2]), "r"(a[3]), "r"(b[0]), "r"(b[1]));
}

// ---------------------------------------------------------------------------
// K0: merged prologue — probe dtype (block 0), zero cursors, prep weights.
// Single deterministic writer of d_flag (block 0, thread 0).
// grid = 1 + 196 + 896 = 1093 blocks of 256.
// ---------------------------------------------------------------------------
__global__ void k_prep(const void* __restrict__ ei,
                       const float* __restrict__ W1, const float* __restrict__ W2) {
    const int b = blockIdx.x, tid = threadIdx.x;
    if (b == 0) {
        const long long v = ((const long long*)ei)[tid];
        int bad = (v < 0 || v >= (long long)N_NODES) ? 1 : 0;
        bad = __syncthreads_or(bad);
        if (tid == 0) d_flag = bad;
    } else if (b <= 196) {
        int i = (b - 1) * 256 + tid;
        if (i < N_NODES) d_cursor[i] = 0;
    } else {
        int i = (b - 197) * 256 + tid;
        const int N1 = HID * DIN;
        if (i < N1) {
            int n = i / DIN, k = i % DIN;
            d_W1p[i] = __half_as_ushort(__float2half_rn(W1[(size_t)k * HID + n]));
        } else {
            int j = i - N1;          // < NODE_OUT*HID by grid sizing
            int n = j / HID, k = j % HID;
            d_W2p[j] = __half_as_ushort(__float2half_rn(W2[(size_t)k * NODE_OUT + n]));
        }
    }
}

// K2: bucket edges by destination node (runs after k_prep)
__global__ void k_bucket(const void* __restrict__ ei) {
    int e = blockIdx.x * blockDim.x + threadIdx.x;
    if (e >= N_EDGES) return;
    int c = d_flag ? ((const int*)ei)[N_EDGES + e]
                   : (int)((const long long*)ei)[N_EDGES + e];
    int pos = atomicAdd(&d_cursor[c], 1);
    if (pos < CAP) d_bucket[c * CAP + pos] = e;
}

// ---------------------------------------------------------------------------
// K3: per-node reduce -> fp16 H row [x | sum | max | mean]
// ---------------------------------------------------------------------------
__global__ void __launch_bounds__(64) k_buildH(const float* __restrict__ x,
                                               const float* __restrict__ edge_attr) {
    __shared__ int se[CAP];
    __shared__ __align__(16) unsigned short rowbuf[DIN];
    const int n = blockIdx.x;
    const int f = threadIdx.x;

    if (n >= N_NODES) {            // zero padding rows for determinism
        uint4* g = (uint4*)(d_A1 + (size_t)n * DIN);
        uint4 z = make_uint4(0, 0, 0, 0);
        for (int w = f; w < DIN / 8; w += 64) g[w] = z;
        return;
    }

    const int total = d_cursor[n];
    const int ec = total < CAP ? total : CAP;
    for (int i = f; i < ec; i += 64) se[i] = d_bucket[n * CAP + i];
    __syncthreads();

    const float NEG_INF = __int_as_float(0xff800000u);
    float s0 = 0.f, s1 = 0.f, s2 = 0.f, s3 = 0.f;
    float m0 = NEG_INF, m1 = NEG_INF, m2 = NEG_INF, m3 = NEG_INF;

    int i = 0;
    for (; i + 4 <= ec; i += 4) {
        float v0 = __ldg(&edge_attr[(size_t)se[i + 0] * EDGE_OUT + f]);
        float v1 = __ldg(&edge_attr[(size_t)se[i + 1] * EDGE_OUT + f]);
        float v2 = __ldg(&edge_attr[(size_t)se[i + 2] * EDGE_OUT + f]);
        float v3 = __ldg(&edge_attr[(size_t)se[i + 3] * EDGE_OUT + f]);
        s0 += v0; s1 += v1; s2 += v2; s3 += v3;
        m0 = fmaxf(m0, v0); m1 = fmaxf(m1, v1);
        m2 = fmaxf(m2, v2); m3 = fmaxf(m3, v3);
    }
    for (; i < ec; i++) {
        float v = __ldg(&edge_attr[(size_t)se[i] * EDGE_OUT + f]);
        s0 += v; m0 = fmaxf(m0, v);
    }
    const float sum = (s0 + s1) + (s2 + s3);
    float mx = fmaxf(fmaxf(m0, m1), fmaxf(m2, m3));
    if (ec == 0) mx = 0.f;
    const float mean = sum / fmaxf((float)total, 1.f);

    float vals[5];
    vals[0] = x[(size_t)n * NODE_IN + f];
    vals[1] = x[(size_t)n * NODE_IN + 64 + f];
    vals[2] = sum; vals[3] = mx; vals[4] = mean;
#pragma unroll
    for (int c5 = 0; c5 < 5; c5++)
        rowbuf[c5 * 64 + f] = __half_as_ushort(__float2half_rn(vals[c5]));
    __syncthreads();

    uint4* g = (uint4*)(d_A1 + (size_t)n * DIN);
    const uint4* s4 = (const uint4*)rowbuf;
    for (int w = f; w < DIN / 8; w += 64) g[w] = s4[w];
}

// ---------------------------------------------------------------------------
// K4/K5: fp16 mma.sync GEMM, 4-slot ring, 2-kt super-iterations:
// ONE __syncthreads + ONE wait_group per 64 K — warps drift across 2 kt,
// amortizing the LDSM burst at each stage boundary.
// MODE 0: CTA 128x128 (2Mx4N warps), relu + fp16 -> d_Hm.
// MODE 1: CTA  64x128, fp32 + bias -> out.
// ---------------------------------------------------------------------------
#define SROW   80                // smem bytes per 32-half row (64B data + 16B pad)
#define NSTAGE 4

template <int MODE>
__global__ void __launch_bounds__(256, 2)
k_mma(const unsigned short* __restrict__ gA, const unsigned short* __restrict__ gB,
      const float* __restrict__ bias, void* __restrict__ outp, int Kp) {
    constexpr int MT   = (MODE == 0) ? 128 : 64;     // M tile
    constexpr int MFR  = (MODE == 0) ? 4 : 2;        // 16-row frags per warp
    constexpr int ATB  = MT * SROW;                  // A tile bytes
    constexpr int STB  = ATB + 128 * SROW;           // stage bytes (A + B)

    extern __shared__ __align__(16) char sm[];
    const int tid = threadIdx.x, L = tid & 31, wid = tid >> 5;
    const int wm = wid >> 2, wn = wid & 3;
    const int n0 = blockIdx.x * 128, row0 = blockIdx.y * MT;
    const uint32_t sb = smem_u32_(sm);

    float acc[MFR][4][4];
#pragma unroll
    for (int a = 0; a < MFR; a++)
#pragma unroll
        for (int b = 0; b < 4; b++)
#pragma unroll
            for (int c = 0; c < 4; c++) acc[a][b][c] = 0.f;

    const int r0c = tid >> 2, q0c = (tid & 3) * 16;                 // chunk 0
    const int r1c = (tid + 256) >> 2, q1c = ((tid + 256) & 3) * 16; // chunk 1

#define LOAD_STAGE(s, k0)                                                        \
    do {                                                                         \
        uint32_t Ab_ = sb + (s) * STB, Bb_ = Ab_ + ATB;                          \
        cpa16(Ab_ + r0c * SROW + q0c, gA + (size_t)(row0 + r0c) * Kp + (k0) + (q0c >> 1)); \
        if constexpr (MT == 128)                                                 \
            cpa16(Ab_ + r1c * SROW + q1c, gA + (size_t)(row0 + r1c) * Kp + (k0) + (q1c >> 1)); \
        cpa16(Bb_ + r0c * SROW + q0c, gB + (size_t)(n0 + r0c) * Kp + (k0) + (q0c >> 1));   \
        cpa16(Bb_ + r1c * SROW + q1c, gB + (size_t)(n0 + r1c) * Kp + (k0) + (q1c >> 1));   \
    } while (0)

    const int NT = Kp >> 5;           // 10 (MODE0) or 16 (MODE1); always even
    // prologue: stages 0 and 1
    LOAD_STAGE(0, 0);  CP_COMMIT();
    LOAD_STAGE(1, 32); CP_COMMIT();

    for (int s2 = 0; s2 < NT; s2 += 2) {
        CP_WAIT0();                   // own copies of stages s2, s2+1 landed
        __syncthreads();              // visibility of all copies + slot-reuse protection

        // issue next super-iteration's stages (slots of s2-2, s2-1: safe after sync)
        if (s2 + 2 < NT) LOAD_STAGE((s2 + 2) & (NSTAGE - 1), (s2 + 2) << 5);
        CP_COMMIT();
        if (s2 + 3 < NT) LOAD_STAGE((s2 + 3) & (NSTAGE - 1), (s2 + 3) << 5);
        CP_COMMIT();

        // compute kt = s2, s2+1 with no intervening barriers
#pragma unroll
        for (int kk = 0; kk < 2; kk++) {
            const int kt = s2 + kk;
            const uint32_t Ab = sb + (kt & (NSTAGE - 1)) * STB;
            const uint32_t Bb = Ab + ATB;
            const uint32_t aBase = Ab + (uint32_t)((wm * (MFR * 16) + (L & 15)) * SROW + ((L >> 4) << 4));
            const uint32_t bBase = Bb + (uint32_t)((wn * 32 + (L & 7) + ((L >> 4) << 3)) * SROW
                                                   + (((L >> 3) & 1) << 4));
#pragma unroll
            for (int ks = 0; ks < 2; ks++) {
                uint32_t afr[MFR][4], bfr[2][4];
#pragma unroll
                for (int mf = 0; mf < MFR; mf++) LDSM4(afr[mf], aBase + mf * 16 * SROW + ks * 32);
#pragma unroll
                for (int nb = 0; nb < 2; nb++) LDSM4(bfr[nb], bBase + nb * 16 * SROW + ks * 32);
#pragma unroll
                for (int mf = 0; mf < MFR; mf++)
#pragma unroll
                    for (int nf = 0; nf < 4; nf++)
                        mma16816(acc[mf][nf], afr[mf], &bfr[nf >> 1][(nf & 1) * 2]);
            }
        }
    }
    __syncthreads();

    if (MODE == 0) {
        // relu + fp16 into d_Hm rows
        unsigned short* gO = (unsigned short*)outp;
        float* st = (float*)sm;
#pragma unroll 1
        for (int half = 0; half < 2; half++) {
            if (wm == half) {
#pragma unroll
                for (int mf = 0; mf < MFR; mf++)
#pragma unroll
                    for (int nf = 0; nf < 4; nf++) {
                        int r = mf * 16 + (L >> 2), c = wn * 32 + nf * 8 + (L & 3) * 2;
                        st[r * 128 + c]           = acc[mf][nf][0];
                        st[r * 128 + c + 1]       = acc[mf][nf][1];
                        st[(r + 8) * 128 + c]     = acc[mf][nf][2];
                        st[(r + 8) * 128 + c + 1] = acc[mf][nf][3];
                    }
            }
            __syncthreads();
            for (int idx = tid; idx < 64 * 16; idx += 256) {
                int r = idx >> 4, w = idx & 15;          // 16 uint4 per row
                uint4 pack;
                unsigned short* t8 = (unsigned short*)&pack;
#pragma unroll
                for (int q = 0; q < 8; q++) {
                    int t = w * 8 + q;
                    float v = st[r * 128 + t] + __ldg(bias + n0 + t);
                    v = fmaxf(v, 0.f);
                    t8[q] = __half_as_ushort(__float2half_rn(v));
                }
                size_t gr = (size_t)(row0 + half * 64 + r);
                *(uint4*)(gO + gr * HID + n0 + w * 8) = pack;
            }
            __syncthreads();
        }
    } else {
        // fp32 + bias, row-guarded
        float* gO = (float*)outp;
#pragma unroll
        for (int mf = 0; mf < MFR; mf++) {
            int r = row0 + wm * (MFR * 16) + mf * 16 + (L >> 2);
#pragma unroll
            for (int nf = 0; nf < 4; nf++) {
                int c = n0 + wn * 32 + nf * 8 + (L & 3) * 2;
                float b0 = __ldg(bias + c), b1 = __ldg(bias + c + 1);
                if (r < N_NODES) {
                    gO[(size_t)r * NODE_OUT + c]     = acc[mf][nf][0] + b0;
                    gO[(size_t)r * NODE_OUT + c + 1] = acc[mf][nf][1] + b1;
                }
                if (r + 8 < N_NODES) {
                    gO[(size_t)(r + 8) * NODE_OUT + c]     = acc[mf][nf][2] + b0;
                    gO[(size_t)(r + 8) * NODE_OUT + c + 1] = acc[mf][nf][3] + b1;
                }
            }
        }
    }
#undef LOAD_STAGE
}

// ---------------------------------------------------------------------------
// Host launcher (graph-capturable: kernel launches only)
// ---------------------------------------------------------------------------
extern "C" void kernel_launch(void* const* d_in, const int* in_sizes, int n_in,
                              void* d_out, int out_size) {
    const float* x         = (const float*)d_in[0];
    const void*  ei        = d_in[1];
    const float* edge_attr = (const float*)d_in[2];
    const float* W1 = (const float*)d_in[5];
    const float* b1 = (const float*)d_in[6];
    const float* W2 = (const float*)d_in[7];
    const float* b2 = (const float*)d_in[8];
    float* out = (float*)d_out;

    void *pA1, *pHm, *pW1p, *pW2p;
    cudaGetSymbolAddress(&pA1, d_A1);
    cudaGetSymbolAddress(&pHm, d_Hm);
    cudaGetSymbolAddress(&pW1p, d_W1p);
    cudaGetSymbolAddress(&pW2p, d_W2p);

    const int SMEM0 = NSTAGE * (128 * SROW + 128 * SROW);   // 81920
    const int SMEM1 = NSTAGE * (64 * SROW + 128 * SROW);    // 61440
    cudaFuncSetAttribute(k_mma<0>, cudaFuncAttributeMaxDynamicSharedMemorySize, SMEM0);
    cudaFuncSetAttribute(k_mma<1>, cudaFuncAttributeMaxDynamicSharedMemorySize, SMEM1);

    // merged prologue: probe + cursor zero + weight prep (1093 blocks)
    k_prep<<<1093, 256>>>(ei, W1, W2);
    k_bucket<<<(N_EDGES + 255) / 256, 256>>>(ei);
    k_buildH<<<MPAD, 64>>>(x, edge_attr);   // MPAD rows (incl. zero pad)

    // GEMM1: [MPAD,320] x [512,320]^T -> relu -> fp16 Hm
    k_mma<0><<<dim3(HID / 128, MPAD / 128), 256, SMEM0>>>(
        (const unsigned short*)pA1, (const unsigned short*)pW1p, b1, pHm, DIN);
    // GEMM2: [MPAD,512] x [128,512]^T -> fp32 out   (64-row tiles: 782 CTAs)
    k_mma<1><<<dim3(NODE_OUT / 128, MPAD / 64), 256, SMEM1>>>(
        (const unsigned short*)pHm, (const unsigned short*)pW2p, b2, out, HID);
}

// round 13
// speedup vs baseline: 1.0275x; 1.0103x over previous
#include <cuda_runtime.h>
#include <cuda_fp16.h>
#include <cstdint>

// ---------------------------------------------------------------------------
// Problem constants
// ---------------------------------------------------------------------------
#define N_NODES  50000
#define N_EDGES  800000
#define NODE_IN  128
#define EDGE_OUT 64
#define DIN      320
#define HID      512
#define NODE_OUT 128
#define CAP      96
#define MPAD     50048          // 391 * 128 (also divisible by 64)

// ---------------------------------------------------------------------------
// Static device scratch (__device__ globals only; no allocations)
// ---------------------------------------------------------------------------
__device__ int d_flag;
__device__ int d_cursor[N_NODES];
__device__ int d_bucket[N_NODES * CAP];
__device__ __align__(16) unsigned short d_A1[(size_t)MPAD * DIN];     // H  (fp16)
__device__ __align__(16) unsigned short d_Hm[(size_t)MPAD * HID];     // relu(HW1+b1) fp16
__device__ __align__(16) unsigned short d_W1p[HID * DIN];             // W1^T fp16
__device__ __align__(16) unsigned short d_W2p[NODE_OUT * HID];        // W2^T fp16

// ---------------------------------------------------------------------------
// Helpers
// ---------------------------------------------------------------------------
__device__ __forceinline__ uint32_t smem_u32_(const void* p) {
    uint32_t a;
    asm("{ .reg .u64 t; cvta.to.shared.u64 t, %1; cvt.u32.u64 %0, t; }" : "=r"(a) : "l"(p));
    return a;
}

__device__ __forceinline__ void cpa16(uint32_t s, const void* g) {
    asm volatile("cp.async.cg.shared.global [%0], [%1], 16;"
                 :: "r"(s), "l"(__cvta_generic_to_global(g)));
}
#define CP_COMMIT() asm volatile("cp.async.commit_group;")
#define CP_WAIT0()  asm volatile("cp.async.wait_group 0;")

#define LDSM4(r, a)                                                          \
    asm volatile("ldmatrix.sync.aligned.m8n8.x4.shared.b16 {%0,%1,%2,%3}, [%4];" \
        : "=r"((r)[0]), "=r"((r)[1]), "=r"((r)[2]), "=r"((r)[3]) : "r"(a))

__device__ __forceinline__ void mma16816(float* c, const uint32_t* a, const uint32_t* b) {
    asm volatile(
        "mma.sync.aligned.m16n8k16.row.col.f32.f16.f16.f32 "
        "{%0,%1,%2,%3}, {%4,%5,%6,%7}, {%8,%9}, {%0,%1,%2,%3};"
        : "+f"(c[0]), "+f"(c[1]), "+f"(c[2]), "+f"(c[3])
        : "r"(a[0]), "r"(a[1]), "r"(a[2]), "r"(a[3]), "r"(b[0]), "r"(b[1]));
}

// ---------------------------------------------------------------------------
// K0: merged prologue — probe dtype (block 0), zero cursors, prep weights.
// ---------------------------------------------------------------------------
__global__ void k_prep(const void* __restrict__ ei,
                       const float* __restrict__ W1, const float* __restrict__ W2) {
    const int b = blockIdx.x, tid = threadIdx.x;
    if (b == 0) {
        const long long v = ((const long long*)ei)[tid];
        int bad = (v < 0 || v >= (long long)N_NODES) ? 1 : 0;
        bad = __syncthreads_or(bad);
        if (tid == 0) d_flag = bad;
    } else if (b <= 196) {
        int i = (b - 1) * 256 + tid;
        if (i < N_NODES) d_cursor[i] = 0;
    } else {
        int i = (b - 197) * 256 + tid;
        const int N1 = HID * DIN;
        if (i < N1) {
            int n = i / DIN, k = i % DIN;
            d_W1p[i] = __half_as_ushort(__float2half_rn(W1[(size_t)k * HID + n]));
        } else {
            int j = i - N1;
            int n = j / HID, k = j % HID;
            d_W2p[j] = __half_as_ushort(__float2half_rn(W2[(size_t)k * NODE_OUT + n]));
        }
    }
}

// K2: bucket edges by destination node (runs after k_prep)
__global__ void k_bucket(const void* __restrict__ ei) {
    int e = blockIdx.x * blockDim.x + threadIdx.x;
    if (e >= N_EDGES) return;
    int c = d_flag ? ((const int*)ei)[N_EDGES + e]
                   : (int)((const long long*)ei)[N_EDGES + e];
    int pos = atomicAdd(&d_cursor[c], 1);
    if (pos < CAP) d_bucket[c * CAP + pos] = e;
}

// ---------------------------------------------------------------------------
// K3: per-node reduce -> fp16 H row [x | sum | max | mean]
// ---------------------------------------------------------------------------
__global__ void __launch_bounds__(64) k_buildH(const float* __restrict__ x,
                                               const float* __restrict__ edge_attr) {
    __shared__ int se[CAP];
    __shared__ __align__(16) unsigned short rowbuf[DIN];
    const int n = blockIdx.x;
    const int f = threadIdx.x;

    if (n >= N_NODES) {
        uint4* g = (uint4*)(d_A1 + (size_t)n * DIN);
        uint4 z = make_uint4(0, 0, 0, 0);
        for (int w = f; w < DIN / 8; w += 64) g[w] = z;
        return;
    }

    const int total = d_cursor[n];
    const int ec = total < CAP ? total : CAP;
    for (int i = f; i < ec; i += 64) se[i] = d_bucket[n * CAP + i];
    __syncthreads();

    const float NEG_INF = __int_as_float(0xff800000u);
    float s0 = 0.f, s1 = 0.f, s2 = 0.f, s3 = 0.f;
    float m0 = NEG_INF, m1 = NEG_INF, m2 = NEG_INF, m3 = NEG_INF;

    int i = 0;
    for (; i + 4 <= ec; i += 4) {
        float v0 = __ldg(&edge_attr[(size_t)se[i + 0] * EDGE_OUT + f]);
        float v1 = __ldg(&edge_attr[(size_t)se[i + 1] * EDGE_OUT + f]);
        float v2 = __ldg(&edge_attr[(size_t)se[i + 2] * EDGE_OUT + f]);
        float v3 = __ldg(&edge_attr[(size_t)se[i + 3] * EDGE_OUT + f]);
        s0 += v0; s1 += v1; s2 += v2; s3 += v3;
        m0 = fmaxf(m0, v0); m1 = fmaxf(m1, v1);
        m2 = fmaxf(m2, v2); m3 = fmaxf(m3, v3);
    }
    for (; i < ec; i++) {
        float v = __ldg(&edge_attr[(size_t)se[i] * EDGE_OUT + f]);
        s0 += v; m0 = fmaxf(m0, v);
    }
    const float sum = (s0 + s1) + (s2 + s3);
    float mx = fmaxf(fmaxf(m0, m1), fmaxf(m2, m3));
    if (ec == 0) mx = 0.f;
    const float mean = sum / fmaxf((float)total, 1.f);

    float vals[5];
    vals[0] = x[(size_t)n * NODE_IN + f];
    vals[1] = x[(size_t)n * NODE_IN + 64 + f];
    vals[2] = sum; vals[3] = mx; vals[4] = mean;
#pragma unroll
    for (int c5 = 0; c5 < 5; c5++)
        rowbuf[c5 * 64 + f] = __half_as_ushort(__float2half_rn(vals[c5]));
    __syncthreads();

    uint4* g = (uint4*)(d_A1 + (size_t)n * DIN);
    const uint4* s4 = (const uint4*)rowbuf;
    for (int w = f; w < DIN / 8; w += 64) g[w] = s4[w];
}

// ---------------------------------------------------------------------------
// K4/K5: fp16 mma.sync GEMM, 4-slot ring, 2-kt super-iterations, and
// register-level frag ping-pong: each super-iter = 4 (kt,ks)-chunks; chunk
// c+1's LDSM issue into the alternate buffer BEFORE chunk c's MMAs, so only
// one LDSM burst per super-iteration is latency-exposed (was four).
// MODE 0: CTA 128x128 (2Mx4N warps), relu + fp16 -> d_Hm.
// MODE 1: CTA  64x128, fp32 + bias -> out.
// ---------------------------------------------------------------------------
#define SROW   80                // smem bytes per 32-half row (64B data + 16B pad)
#define NSTAGE 4

template <int MODE>
__global__ void __launch_bounds__(256, 2)
k_mma(const unsigned short* __restrict__ gA, const unsigned short* __restrict__ gB,
      const float* __restrict__ bias, void* __restrict__ outp, int Kp) {
    constexpr int MT   = (MODE == 0) ? 128 : 64;     // M tile
    constexpr int MFR  = (MODE == 0) ? 4 : 2;        // 16-row frags per warp
    constexpr int ATB  = MT * SROW;                  // A tile bytes
    constexpr int STB  = ATB + 128 * SROW;           // stage bytes (A + B)

    extern __shared__ __align__(16) char sm[];
    const int tid = threadIdx.x, L = tid & 31, wid = tid >> 5;
    const int wm = wid >> 2, wn = wid & 3;
    const int n0 = blockIdx.x * 128, row0 = blockIdx.y * MT;
    const uint32_t sb = smem_u32_(sm);

    float acc[MFR][4][4];
#pragma unroll
    for (int a = 0; a < MFR; a++)
#pragma unroll
        for (int b = 0; b < 4; b++)
#pragma unroll
            for (int c = 0; c < 4; c++) acc[a][b][c] = 0.f;

    const int r0c = tid >> 2, q0c = (tid & 3) * 16;                 // chunk 0
    const int r1c = (tid + 256) >> 2, q1c = ((tid + 256) & 3) * 16; // chunk 1

    // per-warp smem frag offsets (within a stage)
    const uint32_t aoff = (uint32_t)((wm * (MFR * 16) + (L & 15)) * SROW + ((L >> 4) << 4));
    const uint32_t boff = (uint32_t)((wn * 32 + (L & 7) + ((L >> 4) << 3)) * SROW
                                     + (((L >> 3) & 1) << 4));

#define LOAD_STAGE(s, k0)                                                        \
    do {                                                                         \
        uint32_t Ab_ = sb + (s) * STB, Bb_ = Ab_ + ATB;                          \
        cpa16(Ab_ + r0c * SROW + q0c, gA + (size_t)(row0 + r0c) * Kp + (k0) + (q0c >> 1)); \
        if constexpr (MT == 128)                                                 \
            cpa16(Ab_ + r1c * SROW + q1c, gA + (size_t)(row0 + r1c) * Kp + (k0) + (q1c >> 1)); \
        cpa16(Bb_ + r0c * SROW + q0c, gB + (size_t)(n0 + r0c) * Kp + (k0) + (q0c >> 1));   \
        cpa16(Bb_ + r1c * SROW + q1c, gB + (size_t)(n0 + r1c) * Kp + (k0) + (q1c >> 1));   \
    } while (0)

    uint32_t afr[2][MFR][4], bfr[2][2][4];

    // frag loader: buf = ping-pong index, kt = K-stage, ks = 16-wide half
    auto frag_load = [&](int buf, int kt, int ks) {
        const uint32_t Ab_ = sb + (uint32_t)(kt & (NSTAGE - 1)) * STB;
        const uint32_t aB_ = Ab_ + aoff + (uint32_t)(ks << 5);
        const uint32_t bB_ = Ab_ + ATB + boff + (uint32_t)(ks << 5);
#pragma unroll
        for (int mf = 0; mf < MFR; mf++) LDSM4(afr[buf][mf], aB_ + mf * 16 * SROW);
        LDSM4(bfr[buf][0], bB_);
        LDSM4(bfr[buf][1], bB_ + 16 * SROW);
    };

    const int NT = Kp >> 5;           // 10 (MODE0) or 16 (MODE1); always even
    LOAD_STAGE(0, 0);  CP_COMMIT();
    LOAD_STAGE(1, 32); CP_COMMIT();

    for (int s2 = 0; s2 < NT; s2 += 2) {
        CP_WAIT0();                   // stages s2, s2+1 landed
        __syncthreads();              // visibility + slot-reuse protection

        if (s2 + 2 < NT) LOAD_STAGE((s2 + 2) & (NSTAGE - 1), (s2 + 2) << 5);
        CP_COMMIT();
        if (s2 + 3 < NT) LOAD_STAGE((s2 + 3) & (NSTAGE - 1), (s2 + 3) << 5);
        CP_COMMIT();

        // 4 chunks: (kt, ks) = (s2 + (c>>1), c&1); ping-pong frag buffers
        frag_load(0, s2, 0);
#pragma unroll
        for (int c = 0; c < 4; c++) {
            if (c < 3) frag_load((c + 1) & 1, s2 + ((c + 1) >> 1), (c + 1) & 1);
            const int b = c & 1;
#pragma unroll
            for (int mf = 0; mf < MFR; mf++)
#pragma unroll
                for (int nf = 0; nf < 4; nf++)
                    mma16816(acc[mf][nf], afr[b][mf], &bfr[b][nf >> 1][(nf & 1) * 2]);
        }
    }
    __syncthreads();

    if (MODE == 0) {
        // relu + fp16 into d_Hm rows
        unsigned short* gO = (unsigned short*)outp;
        float* st = (float*)sm;
#pragma unroll 1
        for (int half = 0; half < 2; half++) {
            if (wm == half) {
#pragma unroll
                for (int mf = 0; mf < MFR; mf++)
#pragma unroll
                    for (int nf = 0; nf < 4; nf++) {
                        int r = mf * 16 + (L >> 2), c = wn * 32 + nf * 8 + (L & 3) * 2;
                        st[r * 128 + c]           = acc[mf][nf][0];
                        st[r * 128 + c + 1]       = acc[mf][nf][1];
                        st[(r + 8) * 128 + c]     = acc[mf][nf][2];
                        st[(r + 8) * 128 + c + 1] = acc[mf][nf][3];
                    }
            }
            __syncthreads();
            for (int idx = tid; idx < 64 * 16; idx += 256) {
                int r = idx >> 4, w = idx & 15;          // 16 uint4 per row
                uint4 pack;
                unsigned short* t8 = (unsigned short*)&pack;
#pragma unroll
                for (int q = 0; q < 8; q++) {
                    int t = w * 8 + q;
                    float v = st[r * 128 + t] + __ldg(bias + n0 + t);
                    v = fmaxf(v, 0.f);
                    t8[q] = __half_as_ushort(__float2half_rn(v));
                }
                size_t gr = (size_t)(row0 + half * 64 + r);
                *(uint4*)(gO + gr * HID + n0 + w * 8) = pack;
            }
            __syncthreads();
        }
    } else {
        // fp32 + bias, row-guarded
        float* gO = (float*)outp;
#pragma unroll
        for (int mf = 0; mf < MFR; mf++) {
            int r = row0 + wm * (MFR * 16) + mf * 16 + (L >> 2);
#pragma unroll
            for (int nf = 0; nf < 4; nf++) {
                int c = n0 + wn * 32 + nf * 8 + (L & 3) * 2;
                float b0 = __ldg(bias + c), b1 = __ldg(bias + c + 1);
                if (r < N_NODES) {
                    gO[(size_t)r * NODE_OUT + c]     = acc[mf][nf][0] + b0;
                    gO[(size_t)r * NODE_OUT + c + 1] = acc[mf][nf][1] + b1;
                }
                if (r + 8 < N_NODES) {
                    gO[(size_t)(r + 8) * NODE_OUT + c]     = acc[mf][nf][2] + b0;
                    gO[(size_t)(r + 8) * NODE_OUT + c + 1] = acc[mf][nf][3] + b1;
                }
            }
        }
    }
#undef LOAD_STAGE
}

// ---------------------------------------------------------------------------
// Host launcher (graph-capturable: kernel launches only)
// ---------------------------------------------------------------------------
extern "C" void kernel_launch(void* const* d_in, const int* in_sizes, int n_in,
                              void* d_out, int out_size) {
    const float* x         = (const float*)d_in[0];
    const void*  ei        = d_in[1];
    const float* edge_attr = (const float*)d_in[2];
    const float* W1 = (const float*)d_in[5];
    const float* b1 = (const float*)d_in[6];
    const float* W2 = (const float*)d_in[7];
    const float* b2 = (const float*)d_in[8];
    float* out = (float*)d_out;

    void *pA1, *pHm, *pW1p, *pW2p;
    cudaGetSymbolAddress(&pA1, d_A1);
    cudaGetSymbolAddress(&pHm, d_Hm);
    cudaGetSymbolAddress(&pW1p, d_W1p);
    cudaGetSymbolAddress(&pW2p, d_W2p);

    const int SMEM0 = NSTAGE * (128 * SROW + 128 * SROW);   // 81920
    const int SMEM1 = NSTAGE * (64 * SROW + 128 * SROW);    // 61440
    cudaFuncSetAttribute(k_mma<0>, cudaFuncAttributeMaxDynamicSharedMemorySize, SMEM0);
    cudaFuncSetAttribute(k_mma<1>, cudaFuncAttributeMaxDynamicSharedMemorySize, SMEM1);

    // merged prologue: probe + cursor zero + weight prep (1093 blocks)
    k_prep<<<1093, 256>>>(ei, W1, W2);
    k_bucket<<<(N_EDGES + 255) / 256, 256>>>(ei);
    k_buildH<<<MPAD, 64>>>(x, edge_attr);   // MPAD rows (incl. zero pad)

    // GEMM1: [MPAD,320] x [512,320]^T -> relu -> fp16 Hm
    k_mma<0><<<dim3(HID / 128, MPAD / 128), 256, SMEM0>>>(
        (const unsigned short*)pA1, (const unsigned short*)pW1p, b1, pHm, DIN);
    // GEMM2: [MPAD,512] x [128,512]^T -> fp32 out   (64-row tiles: 782 CTAs)
    k_mma<1><<<dim3(NODE_OUT / 128, MPAD / 64), 256, SMEM1>>>(
        (const unsigned short*)pHm, (const unsigned short*)pW2p, b2, out, HID);
}

// round 15
// speedup vs baseline: 1.0439x; 1.0159x over previous
#include <cuda_runtime.h>
#include <cuda_fp16.h>
#include <cstdint>

// ---------------------------------------------------------------------------
// Problem constants
// ---------------------------------------------------------------------------
#define N_NODES  50000
#define N_EDGES  800000
#define NODE_IN  128
#define EDGE_OUT 64
#define DIN      320
#define HID      512
#define NODE_OUT 128
#define CAP      96
#define MPAD     50048          // 391 * 128 (also divisible by 64)
#define NG1      1564           // GEMM1 CTAs: 391 row-blocks x 4 n-blocks
#define NG2      782            // GEMM2 CTAs: 782 64-row blocks
#define NRB      391            // 128-row blocks

// ---------------------------------------------------------------------------
// Static device scratch (__device__ globals only; no allocations)
// ---------------------------------------------------------------------------
__device__ int d_flag;
__device__ int d_cursor[N_NODES];
__device__ int d_ready[NRB];
__device__ int d_bucket[N_NODES * CAP];
__device__ __align__(16) unsigned short d_A1[(size_t)MPAD * DIN];     // H  (fp16)
__device__ __align__(16) unsigned short d_Hm[(size_t)MPAD * HID];     // relu(HW1+b1) fp16
__device__ __align__(16) unsigned short d_W1p[HID * DIN];             // W1^T fp16
__device__ __align__(16) unsigned short d_W2p[NODE_OUT * HID];        // W2^T fp16

// ---------------------------------------------------------------------------
// Helpers
// ---------------------------------------------------------------------------
__device__ __forceinline__ uint32_t smem_u32_(const void* p) {
    uint32_t a;
    asm("{ .reg .u64 t; cvta.to.shared.u64 t, %1; cvt.u32.u64 %0, t; }" : "=r"(a) : "l"(p));
    return a;
}

__device__ __forceinline__ void cpa16(uint32_t s, const void* g) {
    asm volatile("cp.async.cg.shared.global [%0], [%1], 16;"
                 :: "r"(s), "l"(__cvta_generic_to_global(g)));
}
#define CP_COMMIT() asm volatile("cp.async.commit_group;")
#define CP_WAIT0()  asm volatile("cp.async.wait_group 0;")

#define LDSM4(r, a)                                                          \
    asm volatile("ldmatrix.sync.aligned.m8n8.x4.shared.b16 {%0,%1,%2,%3}, [%4];" \
        : "=r"((r)[0]), "=r"((r)[1]), "=r"((r)[2]), "=r"((r)[3]) : "r"(a))

__device__ __forceinline__ void mma16816(float* c, const uint32_t* a, const uint32_t* b) {
    asm volatile(
        "mma.sync.aligned.m16n8k16.row.col.f32.f16.f16.f32 "
        "{%0,%1,%2,%3}, {%4,%5,%6,%7}, {%8,%9}, {%0,%1,%2,%3};"
        : "+f"(c[0]), "+f"(c[1]), "+f"(c[2]), "+f"(c[3])
        : "r"(a[0]), "r"(a[1]), "r"(a[2]), "r"(a[3]), "r"(b[0]), "r"(b[1]));
}

// ---------------------------------------------------------------------------
// K0: merged prologue — probe dtype + zero ready flags (block 0), zero
// cursors, prep weights.
// ---------------------------------------------------------------------------
__global__ void k_prep(const void* __restrict__ ei,
                       const float* __restrict__ W1, const float* __restrict__ W2) {
    const int b = blockIdx.x, tid = threadIdx.x;
    if (b == 0) {
        if (tid < NRB) d_ready[tid] = 0;
        if (tid + 256 < NRB) d_ready[tid + 256] = 0;
        const long long v = ((const long long*)ei)[tid];
        int bad = (v < 0 || v >= (long long)N_NODES) ? 1 : 0;
        bad = __syncthreads_or(bad);
        if (tid == 0) d_flag = bad;
    } else if (b <= 196) {
        int i = (b - 1) * 256 + tid;
        if (i < N_NODES) d_cursor[i] = 0;
    } else {
        int i = (b - 197) * 256 + tid;
        const int N1 = HID * DIN;
        if (i < N1) {
            int n = i / DIN, k = i % DIN;
            d_W1p[i] = __half_as_ushort(__float2half_rn(W1[(size_t)k * HID + n]));
        } else {
            int j = i - N1;
            int n = j / HID, k = j % HID;
            d_W2p[j] = __half_as_ushort(__float2half_rn(W2[(size_t)k * NODE_OUT + n]));
        }
    }
}

// K2: bucket edges by destination node (runs after k_prep)
__global__ void k_bucket(const void* __restrict__ ei) {
    int e = blockIdx.x * blockDim.x + threadIdx.x;
    if (e >= N_EDGES) return;
    int c = d_flag ? ((const int*)ei)[N_EDGES + e]
                   : (int)((const long long*)ei)[N_EDGES + e];
    int pos = atomicAdd(&d_cursor[c], 1);
    if (pos < CAP) d_bucket[c * CAP + pos] = e;
}

// ---------------------------------------------------------------------------
// K3: per-node reduce -> fp16 H row [x | sum | max | mean]
// ---------------------------------------------------------------------------
__global__ void __launch_bounds__(64) k_buildH(const float* __restrict__ x,
                                               const float* __restrict__ edge_attr) {
    __shared__ int se[CAP];
    __shared__ __align__(16) unsigned short rowbuf[DIN];
    const int n = blockIdx.x;
    const int f = threadIdx.x;

    if (n >= N_NODES) {
        uint4* g = (uint4*)(d_A1 + (size_t)n * DIN);
        uint4 z = make_uint4(0, 0, 0, 0);
        for (int w = f; w < DIN / 8; w += 64) g[w] = z;
        return;
    }

    const int total = d_cursor[n];
    const int ec = total < CAP ? total : CAP;
    for (int i = f; i < ec; i += 64) se[i] = d_bucket[n * CAP + i];
    __syncthreads();

    const float NEG_INF = __int_as_float(0xff800000u);
    float s0 = 0.f, s1 = 0.f, s2 = 0.f, s3 = 0.f;
    float m0 = NEG_INF, m1 = NEG_INF, m2 = NEG_INF, m3 = NEG_INF;

    int i = 0;
    for (; i + 4 <= ec; i += 4) {
        float v0 = __ldg(&edge_attr[(size_t)se[i + 0] * EDGE_OUT + f]);
        float v1 = __ldg(&edge_attr[(size_t)se[i + 1] * EDGE_OUT + f]);
        float v2 = __ldg(&edge_attr[(size_t)se[i + 2] * EDGE_OUT + f]);
        float v3 = __ldg(&edge_attr[(size_t)se[i + 3] * EDGE_OUT + f]);
        s0 += v0; s1 += v1; s2 += v2; s3 += v3;
        m0 = fmaxf(m0, v0); m1 = fmaxf(m1, v1);
        m2 = fmaxf(m2, v2); m3 = fmaxf(m3, v3);
    }
    for (; i < ec; i++) {
        float v = __ldg(&edge_attr[(size_t)se[i] * EDGE_OUT + f]);
        s0 += v; m0 = fmaxf(m0, v);
    }
    const float sum = (s0 + s1) + (s2 + s3);
    float mx = fmaxf(fmaxf(m0, m1), fmaxf(m2, m3));
    if (ec == 0) mx = 0.f;
    const float mean = sum / fmaxf((float)total, 1.f);

    float vals[5];
    vals[0] = x[(size_t)n * NODE_IN + f];
    vals[1] = x[(size_t)n * NODE_IN + 64 + f];
    vals[2] = sum; vals[3] = mx; vals[4] = mean;
#pragma unroll
    for (int c5 = 0; c5 < 5; c5++)
        rowbuf[c5 * 64 + f] = __half_as_ushort(__float2half_rn(vals[c5]));
    __syncthreads();

    uint4* g = (uint4*)(d_A1 + (size_t)n * DIN);
    const uint4* s4 = (const uint4*)rowbuf;
    for (int w = f; w < DIN / 8; w += 64) g[w] = s4[w];
}

// ---------------------------------------------------------------------------
// GEMM body (device function). 4-slot ring, 2-kt super-iters, frag ping-pong.
// MODE 0: 128x128 tile, relu + fp16 -> d_Hm. MODE 1: 64x128 tile, fp32 -> out.
// ---------------------------------------------------------------------------
#define SROW   80
#define NSTAGE 4

template <int MODE>
__device__ __forceinline__ void gemm_body(
    char* sm, int row0, int n0,
    const unsigned short* __restrict__ gA, const unsigned short* __restrict__ gB,
    const float* __restrict__ bias, void* __restrict__ outp, int Kp) {
    constexpr int MT   = (MODE == 0) ? 128 : 64;
    constexpr int MFR  = (MODE == 0) ? 4 : 2;
    constexpr int ATB  = MT * SROW;
    constexpr int STB  = ATB + 128 * SROW;

    const int tid = threadIdx.x, L = tid & 31, wid = tid >> 5;
    const int wm = wid >> 2, wn = wid & 3;
    const uint32_t sb = smem_u32_(sm);

    float acc[MFR][4][4];
#pragma unroll
    for (int a = 0; a < MFR; a++)
#pragma unroll
        for (int b = 0; b < 4; b++)
#pragma unroll
            for (int c = 0; c < 4; c++) acc[a][b][c] = 0.f;

    const int r0c = tid >> 2, q0c = (tid & 3) * 16;
    const int r1c = (tid + 256) >> 2, q1c = ((tid + 256) & 3) * 16;

    const uint32_t aoff = (uint32_t)((wm * (MFR * 16) + (L & 15)) * SROW + ((L >> 4) << 4));
    const uint32_t boff = (uint32_t)((wn * 32 + (L & 7) + ((L >> 4) << 3)) * SROW
                                     + (((L >> 3) & 1) << 4));

#define LOAD_STAGE(s, k0)                                                        \
    do {                                                                         \
        uint32_t Ab_ = sb + (s) * STB, Bb_ = Ab_ + ATB;                          \
        cpa16(Ab_ + r0c * SROW + q0c, gA + (size_t)(row0 + r0c) * Kp + (k0) + (q0c >> 1)); \
        if constexpr (MT == 128)                                                 \
            cpa16(Ab_ + r1c * SROW + q1c, gA + (size_t)(row0 + r1c) * Kp + (k0) + (q1c >> 1)); \
        cpa16(Bb_ + r0c * SROW + q0c, gB + (size_t)(n0 + r0c) * Kp + (k0) + (q0c >> 1));   \
        cpa16(Bb_ + r1c * SROW + q1c, gB + (size_t)(n0 + r1c) * Kp + (k0) + (q1c >> 1));   \
    } while (0)

    uint32_t afr[2][MFR][4], bfr[2][2][4];

    auto frag_load = [&](int buf, int kt, int ks) {
        const uint32_t Ab_ = sb + (uint32_t)(kt & (NSTAGE - 1)) * STB;
        const uint32_t aB_ = Ab_ + aoff + (uint32_t)(ks << 5);
        const uint32_t bB_ = Ab_ + ATB + boff + (uint32_t)(ks << 5);
#pragma unroll
        for (int mf = 0; mf < MFR; mf++) LDSM4(afr[buf][mf], aB_ + mf * 16 * SROW);
        LDSM4(bfr[buf][0], bB_);
        LDSM4(bfr[buf][1], bB_ + 16 * SROW);
    };

    const int NT = Kp >> 5;
    LOAD_STAGE(0, 0);  CP_COMMIT();
    LOAD_STAGE(1, 32); CP_COMMIT();

    for (int s2 = 0; s2 < NT; s2 += 2) {
        CP_WAIT0();
        __syncthreads();

        if (s2 + 2 < NT) LOAD_STAGE((s2 + 2) & (NSTAGE - 1), (s2 + 2) << 5);
        CP_COMMIT();
        if (s2 + 3 < NT) LOAD_STAGE((s2 + 3) & (NSTAGE - 1), (s2 + 3) << 5);
        CP_COMMIT();

        frag_load(0, s2, 0);
#pragma unroll
        for (int c = 0; c < 4; c++) {
            if (c < 3) frag_load((c + 1) & 1, s2 + ((c + 1) >> 1), (c + 1) & 1);
            const int b = c & 1;
#pragma unroll
            for (int mf = 0; mf < MFR; mf++)
#pragma unroll
                for (int nf = 0; nf < 4; nf++)
                    mma16816(acc[mf][nf], afr[b][mf], &bfr[b][nf >> 1][(nf & 1) * 2]);
        }
    }
    __syncthreads();

    if (MODE == 0) {
        unsigned short* gO = (unsigned short*)outp;
        float* st = (float*)sm;
#pragma unroll 1
        for (int half = 0; half < 2; half++) {
            if (wm == half) {
#pragma unroll
                for (int mf = 0; mf < MFR; mf++)
#pragma unroll
                    for (int nf = 0; nf < 4; nf++) {
                        int r = mf * 16 + (L >> 2), c = wn * 32 + nf * 8 + (L & 3) * 2;
                        st[r * 128 + c]           = acc[mf][nf][0];
                        st[r * 128 + c + 1]       = acc[mf][nf][1];
                        st[(r + 8) * 128 + c]     = acc[mf][nf][2];
                        st[(r + 8) * 128 + c + 1] = acc[mf][nf][3];
                    }
            }
            __syncthreads();
            for (int idx = tid; idx < 64 * 16; idx += 256) {
                int r = idx >> 4, w = idx & 15;
                uint4 pack;
                unsigned short* t8 = (unsigned short*)&pack;
#pragma unroll
                for (int q = 0; q < 8; q++) {
                    int t = w * 8 + q;
                    float v = st[r * 128 + t] + __ldg(bias + n0 + t);
                    v = fmaxf(v, 0.f);
                    t8[q] = __half_as_ushort(__float2half_rn(v));
                }
                size_t gr = (size_t)(row0 + half * 64 + r);
                *(uint4*)(gO + gr * HID + n0 + w * 8) = pack;
            }
            __syncthreads();
        }
    } else {
        float* gO = (float*)outp;
#pragma unroll
        for (int mf = 0; mf < MFR; mf++) {
            int r = row0 + wm * (MFR * 16) + mf * 16 + (L >> 2);
#pragma unroll
            for (int nf = 0; nf < 4; nf++) {
                int c = n0 + wn * 32 + nf * 8 + (L & 3) * 2;
                float b0 = __ldg(bias + c), b1 = __ldg(bias + c + 1);
                if (r < N_NODES) {
                    gO[(size_t)r * NODE_OUT + c]     = acc[mf][nf][0] + b0;
                    gO[(size_t)r * NODE_OUT + c + 1] = acc[mf][nf][1] + b1;
                }
                if (r + 8 < N_NODES) {
                    gO[(size_t)(r + 8) * NODE_OUT + c]     = acc[mf][nf][2] + b0;
                    gO[(size_t)(r + 8) * NODE_OUT + c + 1] = acc[mf][nf][3] + b1;
                }
            }
        }
    }
#undef LOAD_STAGE
}

// ---------------------------------------------------------------------------
// K4: fused MLP launch. bids [0,NG1): GEMM1 tiles + publish ready flag.
// bids [NG1, NG1+NG2): GEMM2 64-row tiles, wait on 4 producers (lower bids ->
// scheduled earlier -> no deadlock; stream-K-style fixup pattern).
// ---------------------------------------------------------------------------
#define SMEM_MLP (NSTAGE * (128 * SROW + 128 * SROW))   // 81920

__global__ void __launch_bounds__(256, 2)
k_mlp(const unsigned short* __restrict__ gA1, const unsigned short* __restrict__ gW1,
      const unsigned short* __restrict__ gW2,
      const float* __restrict__ b1v, const float* __restrict__ b2v,
      unsigned short* __restrict__ hm, float* __restrict__ outp) {
    extern __shared__ __align__(16) char sm[];
    const int bid = blockIdx.x, tid = threadIdx.x;

    if (bid < NG1) {
        const int gy = bid >> 2, n0 = (bid & 3) << 7;
        gemm_body<0>(sm, gy << 7, n0, gA1, gW1, b1v, hm, DIN);
        __syncthreads();                       // all epilogue STGs issued
        if (tid == 0) {
            __threadfence();                   // order Hm writes before flag
            atomicAdd(&d_ready[gy], 1);
        }
    } else {
        const int b2 = bid - NG1;              // 0..781
        const int gy = b2 >> 1;                // producer 128-row block
        if (tid == 0) {
            while (atomicAdd(&d_ready[gy], 0) < 4) __nanosleep(100);
        }
        __syncthreads();
        __threadfence();                       // acquire Hm writes
        gemm_body<1>(sm, b2 << 6, 0, hm, gW2, b2v, outp, HID);
    }
}

// ---------------------------------------------------------------------------
// Host launcher (graph-capturable: kernel launches only)
// ---------------------------------------------------------------------------
extern "C" void kernel_launch(void* const* d_in, const int* in_sizes, int n_in,
                              void* d_out, int out_size) {
    const float* x         = (const float*)d_in[0];
    const void*  ei        = d_in[1];
    const float* edge_attr = (const float*)d_in[2];
    const float* W1 = (const float*)d_in[5];
    const float* b1 = (const float*)d_in[6];
    const float* W2 = (const float*)d_in[7];
    const float* b2 = (const float*)d_in[8];
    float* out = (float*)d_out;

    void *pA1, *pHm, *pW1p, *pW2p;
    cudaGetSymbolAddress(&pA1, d_A1);
    cudaGetSymbolAddress(&pHm, d_Hm);
    cudaGetSymbolAddress(&pW1p, d_W1p);
    cudaGetSymbolAddress(&pW2p, d_W2p);

    cudaFuncSetAttribute(k_mlp, cudaFuncAttributeMaxDynamicSharedMemorySize, SMEM_MLP);

    // merged prologue: probe + ready/cursor zero + weight prep (1093 blocks)
    k_prep<<<1093, 256>>>(ei, W1, W2);
    k_bucket<<<(N_EDGES + 255) / 256, 256>>>(ei);
    k_buildH<<<MPAD, 64>>>(x, edge_attr);   // MPAD rows (incl. zero pad)

    // Fused MLP: GEMM1 tiles (bids 0..1563) + GEMM2 tiles (bids 1564..2345)
    k_mlp<<<NG1 + NG2, 256, SMEM_MLP>>>(
        (const unsigned short*)pA1, (const unsigned short*)pW1p,
        (const unsigned short*)pW2p, b1, b2, (unsigned short*)pHm, out);
}